// round 1
// baseline (speedup 1.0000x reference)
#include <cuda_runtime.h>

// IF neuron multi-step scan, hard reset:
//   h_t = x_t + v_{t-1};  s_t = (h_t - 1 >= 0) ? 1 : 0;  v_t = s_t ? 0 : h_t
// One thread owns 4 contiguous (b,d) lanes (float4), loops serially over T.
// Loads/stores are fully coalesced at every t (stride between timesteps is N).

__global__ __launch_bounds__(256) void if_scan_kernel(
    const float4* __restrict__ x,   // [T, N/4] viewed as float4
    const float4* __restrict__ v0,  // [N/4]
    float4* __restrict__ out,       // [T, N/4]
    int n4, int T)
{
    int i = blockIdx.x * blockDim.x + threadIdx.x;
    if (i >= n4) return;

    float4 v = v0[i];

    const float4* xp = x + i;
    float4* op = out + i;

    // T is 32 for this problem; unroll by 4 so the compiler batches the
    // independent loads of future timesteps ahead of the v-recurrence.
    #pragma unroll 4
    for (int t = 0; t < T; ++t) {
        float4 xv = __ldg(xp);
        xp += n4;

        float h0 = xv.x + v.x;
        float h1 = xv.y + v.y;
        float h2 = xv.z + v.z;
        float h3 = xv.w + v.w;

        float s0 = (h0 >= 1.0f) ? 1.0f : 0.0f;
        float s1 = (h1 >= 1.0f) ? 1.0f : 0.0f;
        float s2 = (h2 >= 1.0f) ? 1.0f : 0.0f;
        float s3 = (h3 >= 1.0f) ? 1.0f : 0.0f;

        v.x = (h0 >= 1.0f) ? 0.0f : h0;
        v.y = (h1 >= 1.0f) ? 0.0f : h1;
        v.z = (h2 >= 1.0f) ? 0.0f : h2;
        v.w = (h3 >= 1.0f) ? 0.0f : h3;

        *op = make_float4(s0, s1, s2, s3);
        op += n4;
    }
}

extern "C" void kernel_launch(void* const* d_in, const int* in_sizes, int n_in,
                              void* d_out, int out_size)
{
    const float* x_seq  = (const float*)d_in[0];   // [T, B, D]
    const float* v_init = (const float*)d_in[1];   // [B, D]

    int N = in_sizes[1];              // B * D
    int T = in_sizes[0] / N;          // timesteps
    int n4 = N / 4;                   // N = 128*8192, divisible by 4

    int block = 256;
    int grid = (n4 + block - 1) / block;

    if_scan_kernel<<<grid, block>>>(
        (const float4*)x_seq,
        (const float4*)v_init,
        (float4*)d_out,
        n4, T);
}